// round 1
// baseline (speedup 1.0000x reference)
#include <cuda_runtime.h>
#include <cstdint>

// ---------------------------------------------------------------------------
// GhInfer_19104014533112 : YOLO NMS post-process on GB300
// Outputs (flattened, in reference-return order):
//   [0      : 6000)    det  (1000 x 6)  float32
//   [6000   : 1234800) x    (1 x 3 x 640 x 640) float32
// Inputs:
//   d_in[0] img  int32  (640*640*3)
//   d_in[1] pred float32 (8*25200*85)  -- only batch 0 used
// ---------------------------------------------------------------------------

#define NANCH 25200
#define NCLS  80
#define KTOP  2048
#define NBINS 16384
#define CAP   8192
#define MAXDET 1000
#define CONF_T 0.4f
#define IOU_T  0.45f
#define IMG_ELEMS (640*640*3)

// ------------------------- device scratch (no allocs) ----------------------
__device__ unsigned int        g_msc[NANCH];     // monotone-mapped score bits
__device__ int                 g_cls[NANCH];     // argmax class
__device__ int                 g_hist[NBINS];
__device__ unsigned int        g_thresh;         // threshold bin
__device__ int                 g_count;
__device__ unsigned long long  g_keys[CAP];
__device__ float4              g_box[KTOP];      // xyxy (no class offset)
__device__ float4              g_boff[KTOP];     // xyxy + class*7680
__device__ float               g_area[KTOP];     // area from offset coords
__device__ float               g_sc[KTOP];
__device__ float               g_cf[KTOP];
__device__ unsigned long long  g_mask[KTOP*32];  // suppression bitmask rows
__device__ unsigned long long  g_rem0[32];       // initial removed bits
__device__ unsigned long long  g_remF[32];       // final removed bits

// monotone float -> uint mapping (order-preserving over all finite floats)
__device__ __forceinline__ unsigned int f2u(float f) {
    unsigned int b = __float_as_uint(f);
    return (b & 0x80000000u) ? ~b : (b | 0x80000000u);
}
__device__ __forceinline__ float u2f(unsigned int u) {
    unsigned int b = (u & 0x80000000u) ? (u ^ 0x80000000u) : ~u;
    return __uint_as_float(b);
}

// ------------------------------ kernels ------------------------------------

__global__ void k_img(const int* __restrict__ img, float* __restrict__ out) {
    int i = blockIdx.x * blockDim.x + threadIdx.x;
    if (i >= IMG_ELEMS) return;
    int c  = i / (640 * 640);
    int px = i - c * (640 * 640);
    // x[c][h][w] = img[h][w][2-c] / 255
    out[6000 + i] = (float)img[px * 3 + (2 - c)] / 255.0f;
}

__global__ void k_zero() {
    int i = blockIdx.x * blockDim.x + threadIdx.x;
    if (i < NBINS) g_hist[i] = 0;
    if (i < CAP)   g_keys[i] = 0ULL;
    if (i < 32)    g_rem0[i] = 0ULL;
    if (i == 0)    g_count   = 0;
}

__global__ void k_scores(const float* __restrict__ pred) {
    int i = blockIdx.x * blockDim.x + threadIdx.x;
    if (i >= NANCH) return;
    const float* r = pred + (long long)i * 85;
    float obj = r[4];
    float m   = __fmul_rn(r[5], obj);
    int   cls = 0;
#pragma unroll 4
    for (int c = 1; c < NCLS; ++c) {
        float v = __fmul_rn(r[5 + c], obj);
        if (v > m) { m = v; cls = c; }   // strict > keeps first max (jnp.argmax)
    }
    float sc = (m > CONF_T) ? m : -1.0f;
    unsigned int u = f2u(sc);
    g_msc[i] = u;
    g_cls[i] = cls;
    atomicAdd(&g_hist[u >> 18], 1);
}

__global__ void k_thresh() {
    __shared__ int part[1024];
    int t = threadIdx.x;
    int s = 0;
#pragma unroll
    for (int b = 0; b < 16; ++b) s += g_hist[t * 16 + b];
    part[t] = s;
    __syncthreads();
    if (t == 0) {
        int acc = 0;
        unsigned int th = 0;
        for (int q = 1023; q >= 0; --q) {
            if (acc + part[q] >= KTOP) {
                for (int b = q * 16 + 15; b >= q * 16; --b) {
                    acc += g_hist[b];
                    if (acc >= KTOP) { th = (unsigned int)b; break; }
                }
                break;
            }
            acc += part[q];
        }
        g_thresh = th;
    }
}

__global__ void k_compact() {
    int i = blockIdx.x * blockDim.x + threadIdx.x;
    if (i >= NANCH) return;
    unsigned int u = g_msc[i];
    if ((u >> 18) >= g_thresh) {
        int p = atomicAdd(&g_count, 1);
        if (p < CAP)
            g_keys[p] = ((unsigned long long)u << 32) | (unsigned int)(~i);
    }
}

// single-block bitonic sort, descending, n chosen at runtime (4096 or 8192)
__global__ void k_sort() {
    extern __shared__ unsigned long long sk[];
    int tid = threadIdx.x;
    int cnt = g_count;
    int n = (cnt <= 4096) ? 4096 : 8192;
    for (int i = tid; i < n; i += 1024) sk[i] = g_keys[i];
    __syncthreads();
    for (int k = 2; k <= n; k <<= 1) {
        for (int j = k >> 1; j > 0; j >>= 1) {
            for (int i = tid; i < n; i += 1024) {
                int x = i ^ j;
                if (x > i) {
                    unsigned long long a = sk[i], b = sk[x];
                    bool desc = ((i & k) == 0);
                    if (desc ? (a < b) : (a > b)) { sk[i] = b; sk[x] = a; }
                }
            }
            __syncthreads();
        }
    }
    for (int i = tid; i < KTOP; i += 1024) g_keys[i] = sk[i];
}

__global__ void k_gather(const float* __restrict__ pred) {
    int r = blockIdx.x * blockDim.x + threadIdx.x;
    if (r >= KTOP) return;
    unsigned long long key = g_keys[r];
    float sc;
    int idx;
    if (key == 0ULL) { sc = -1.0f; idx = 0; }          // padding (shouldn't occur)
    else {
        sc  = u2f((unsigned int)(key >> 32));
        idx = (int)(~(unsigned int)key);
    }
    const float* p = pred + (long long)idx * 85;
    float x = p[0], y = p[1], w = p[2], h = p[3];
    float hw = __fmul_rn(w, 0.5f), hh = __fmul_rn(h, 0.5f);
    float x1 = __fsub_rn(x, hw), y1 = __fsub_rn(y, hh);
    float x2 = __fadd_rn(x, hw), y2 = __fadd_rn(y, hh);
    int   cls = g_cls[idx];
    float cf  = (float)cls;
    float off = __fmul_rn(cf, 7680.0f);
    float ox1 = __fadd_rn(x1, off), oy1 = __fadd_rn(y1, off);
    float ox2 = __fadd_rn(x2, off), oy2 = __fadd_rn(y2, off);
    g_box[r]  = make_float4(x1, y1, x2, y2);
    g_boff[r] = make_float4(ox1, oy1, ox2, oy2);
    g_area[r] = __fmul_rn(__fsub_rn(ox2, ox1), __fsub_rn(oy2, oy1));
    g_sc[r] = sc;
    g_cf[r] = cf;
    if (!(sc > CONF_T))
        atomicOr(&g_rem0[r >> 6], 1ULL << (r & 63));
}

// suppression bitmask: bit (i, j) set iff j > i and IoU(boff_i, boff_j) > 0.45
__global__ void __launch_bounds__(256) k_iou() {
    __shared__ float4 sb[KTOP];
    __shared__ float  sa[KTOP];
    for (int kx = threadIdx.x; kx < KTOP; kx += 256) {
        sb[kx] = g_boff[kx];
        sa[kx] = g_area[kx];
    }
    __syncthreads();
    int t = blockIdx.x * 256 + threadIdx.x;   // 65536 threads total
    int i = t >> 5, w = t & 31;
    float4 a  = sb[i];
    float  fa = sa[i];
    unsigned long long bits = 0ULL;
    int j0 = w << 6;
    for (int jj = 0; jj < 64; ++jj) {
        int j = j0 + jj;
        if (j <= i) continue;
        float4 b = sb[j];
        float ltx = fmaxf(a.x, b.x), lty = fmaxf(a.y, b.y);
        float rbx = fminf(a.z, b.z), rby = fminf(a.w, b.w);
        float wx = fmaxf(__fsub_rn(rbx, ltx), 0.0f);
        float wy = fmaxf(__fsub_rn(rby, lty), 0.0f);
        float inter = __fmul_rn(wx, wy);
        float den = __fadd_rn(__fsub_rn(__fadd_rn(fa, sa[j]), inter), 1e-7f);
        float iou = __fdiv_rn(inter, den);
        if (iou > IOU_T) bits |= (1ULL << jj);
    }
    g_mask[i * 32 + w] = bits;
}

// greedy sequential NMS, chunked: 32-row chunks keep the dependent chain in
// registers (diagonal word only), full-row mask ORs are independent LDGs.
__global__ void k_nms() {
    int lane = threadIdx.x;                       // 32 threads
    __shared__ unsigned long long rems[32];
    __shared__ unsigned long long dm[32];
    unsigned long long rem = g_rem0[lane];
    rems[lane] = rem;
    __syncwarp();
    for (int c = 0; c < 64; ++c) {
        int base = c << 5;
        int wd   = c >> 1;
        int half = (c & 1) << 5;
        // diagonal word for each of this chunk's 32 rows
        dm[lane] = g_mask[(unsigned)(base + lane) * 32 + wd];
        __syncwarp();
        unsigned long long r = rems[wd];
        unsigned kmask = 0;
#pragma unroll
        for (int b = 0; b < 32; ++b) {
            if (!((r >> (half + b)) & 1ULL)) {
                r |= dm[b];
                kmask |= (1u << b);
            }
        }
        // apply kept rows' full masks (independent coalesced loads)
        unsigned long long acc = 0ULL;
#pragma unroll 8
        for (int b = 0; b < 32; ++b) {
            unsigned long long v = g_mask[(unsigned)(base + b) * 32 + lane];
            if (kmask & (1u << b)) acc |= v;
        }
        rem |= acc;
        rems[lane] = rem;
        __syncwarp();
    }
    g_remF[lane] = rem;
}

__global__ void k_final(float* __restrict__ out) {
    __shared__ int wpre[32];
    int tid = threadIdx.x;
    if (tid == 0) {
        int s = 0;
        for (int w = 0; w < 32; ++w) {
            wpre[w] = s;
            s += __popcll(~g_remF[w]);
        }
    }
    for (int i = tid; i < MAXDET * 6; i += 1024) out[i] = 0.0f;
    __syncthreads();
    for (int r = tid; r < KTOP; r += 1024) {
        unsigned long long kb = ~g_remF[r >> 6];
        if ((kb >> (r & 63)) & 1ULL) {
            int pos = wpre[r >> 6] + __popcll(kb & ((1ULL << (r & 63)) - 1ULL));
            if (pos < MAXDET) {
                float4 b = g_box[r];
                out[pos * 6 + 0] = b.x;
                out[pos * 6 + 1] = b.y;
                out[pos * 6 + 2] = b.z;
                out[pos * 6 + 3] = b.w;
                out[pos * 6 + 4] = g_sc[r];
                out[pos * 6 + 5] = g_cf[r];
            }
        }
    }
}

// ------------------------------ launch --------------------------------------

extern "C" void kernel_launch(void* const* d_in, const int* in_sizes, int n_in,
                              void* d_out, int out_size) {
    const int*   img  = (const int*)d_in[0];
    const float* pred = (const float*)d_in[1];
    float*       out  = (float*)d_out;

    cudaFuncSetAttribute(k_sort, cudaFuncAttributeMaxDynamicSharedMemorySize, 65536);

    k_img    <<< (IMG_ELEMS + 255) / 256, 256 >>> (img, out);
    k_zero   <<< (NBINS + 255) / 256, 256 >>> ();
    k_scores <<< (NANCH + 255) / 256, 256 >>> (pred);
    k_thresh <<< 1, 1024 >>> ();
    k_compact<<< (NANCH + 255) / 256, 256 >>> ();
    k_sort   <<< 1, 1024, 65536 >>> ();
    k_gather <<< 2, 1024 >>> (pred);
    k_iou    <<< 256, 256 >>> ();
    k_nms    <<< 1, 32 >>> ();
    k_final  <<< 1, 1024 >>> (out);
}

// round 2
// speedup vs baseline: 1.9040x; 1.9040x over previous
#include <cuda_runtime.h>
#include <cstdint>

typedef unsigned long long u64;
typedef unsigned int u32;

// ---------------------------------------------------------------------------
// GhInfer_19104014533112 : YOLO NMS post-process on GB300
// out[0:6000) det (1000x6) fp32 ; out[6000:1234800) img (1,3,640,640) fp32
// in[0] img int32 (640*640*3) ; in[1] pred fp32 (8*25200*85), batch 0 only
// ---------------------------------------------------------------------------

#define NANCH 25200
#define NCLS  80
#define KTOP  2048
#define NBINS 16384
#define CAP   8192
#define MAXDET 1000
#define CONF_T 0.4f
#define IOU_T  0.45f
#define IMG_ELEMS (640*640*3)

// ------------------------- device scratch (no allocs) ----------------------
__device__ u32    g_msc[NANCH];
__device__ int    g_cls[NANCH];
__device__ int    g_hist[NBINS];
__device__ u32    g_thresh;
__device__ int    g_count;
__device__ u64    g_keys[CAP];
__device__ int    g_rank[CAP];
__device__ float4 g_box[KTOP];
__device__ float4 g_boff[KTOP];
__device__ float  g_area[KTOP];
__device__ float  g_sc[KTOP];
__device__ float  g_cf[KTOP];
__device__ u64    g_mask[KTOP*32];
__device__ u64    g_rem0[32];

__device__ __forceinline__ u32 f2u(float f) {
    u32 b = __float_as_uint(f);
    return (b & 0x80000000u) ? ~b : (b | 0x80000000u);
}
__device__ __forceinline__ float u2f(u32 u) {
    u32 b = (u & 0x80000000u) ? (u ^ 0x80000000u) : ~u;
    return __uint_as_float(b);
}

// ---------------------------------------------------------------------------
// 1. image preprocess + all zeroing / padding (independent of pred pipeline)
__global__ void k_pre(const int* __restrict__ img, float* __restrict__ out) {
    int i = blockIdx.x * 256 + threadIdx.x;
    if (i < IMG_ELEMS) {
        int c  = i / (640 * 640);
        int px = i - c * (640 * 640);
        out[6000 + i] = (float)img[px * 3 + (2 - c)] / 255.0f;
    }
    if (i < 6000)  out[i] = 0.0f;
    if (i < NBINS) g_hist[i] = 0;
    if (i < CAP) {
        g_keys[i] = (u64)(u32)i;   // unique pad keys, sort below all real keys
        g_rank[i] = 0;
    }
    if (i < 32) g_rem0[i] = 0ULL;
    if (i == 0) g_count = 0;
}

// 2. per-anchor score/argmax + 14-bit histogram
__global__ void k_scores(const float* __restrict__ pred) {
    int i = blockIdx.x * blockDim.x + threadIdx.x;
    if (i >= NANCH) return;
    const float* r = pred + (long long)i * 85;
    float obj = r[4];
    float m   = __fmul_rn(r[5], obj);
    int   cls = 0;
#pragma unroll 8
    for (int c = 1; c < NCLS; ++c) {
        float v = __fmul_rn(r[5 + c], obj);
        if (v > m) { m = v; cls = c; }   // strict > keeps first max (jnp.argmax)
    }
    float sc = (m > CONF_T) ? m : -1.0f;
    u32 u = f2u(sc);
    g_msc[i] = u;
    g_cls[i] = cls;
    atomicAdd(&g_hist[u >> 18], 1);
}

// 3. threshold bin: parallel suffix-scan over 1024 groups of 16 bins
__global__ void k_thresh() {
    __shared__ int part[1024];
    int t = threadIdx.x;
    int s = 0;
#pragma unroll
    for (int b = 0; b < 16; ++b) s += g_hist[t * 16 + b];
    part[t] = s;
    __syncthreads();
    for (int off = 1; off < 1024; off <<= 1) {
        int v = (t + off < 1024) ? part[t + off] : 0;
        __syncthreads();
        part[t] += v;
        __syncthreads();
    }
    // part[t] = suffix count over bins >= t*16 (monotone decreasing in t)
    int nxt = (t < 1023) ? part[t + 1] : 0;
    if (part[t] >= KTOP && nxt < KTOP) {
        int acc = nxt;
        for (int b = t * 16 + 15; b >= t * 16; --b) {
            acc += g_hist[b];
            if (acc >= KTOP) { g_thresh = (u32)b; break; }
        }
    }
}

// 4. compact candidates whose bin >= threshold bin
__global__ void k_compact() {
    int i = blockIdx.x * blockDim.x + threadIdx.x;
    if (i >= NANCH) return;
    u32 u = g_msc[i];
    if ((u >> 18) >= g_thresh) {
        int p = atomicAdd(&g_count, 1);
        if (p < CAP)
            g_keys[p] = ((u64)u << 32) | (u32)(~i);
    }
}

// 5. rank-sort: rank[i] = #{j : key[j] > key[i]} (keys unique => exact top_k)
__global__ void k_rank() {
    __shared__ u64 sk[1024];
    int tid = threadIdx.x;
    sk[tid] = g_keys[blockIdx.y * 1024 + tid];
    __syncthreads();
    int i = blockIdx.x * 1024 + tid;
    u64 my = g_keys[i];
    int cnt = 0;
#pragma unroll 16
    for (int j = 0; j < 1024; ++j)        // uniform j => smem broadcast
        cnt += (sk[j] > my) ? 1 : 0;
    if (cnt) atomicAdd(&g_rank[i], cnt);
}

// 6. scatter by rank + box decode (fused "gather")
__global__ void k_gather(const float* __restrict__ pred) {
    int i = blockIdx.x * 1024 + threadIdx.x;
    int r = g_rank[i];
    if (r >= KTOP) return;
    u64 key = g_keys[i];
    u32 hi = (u32)(key >> 32);
    float sc; int idx;
    if (hi == 0u) { sc = -1.0f; idx = 0; }            // pad (cnt<2048 never)
    else          { sc = u2f(hi); idx = (int)(~(u32)key); }
    const float* p = pred + (long long)idx * 85;
    float x = p[0], y = p[1], w = p[2], h = p[3];
    float hw = __fmul_rn(w, 0.5f), hh = __fmul_rn(h, 0.5f);
    float x1 = __fsub_rn(x, hw), y1 = __fsub_rn(y, hh);
    float x2 = __fadd_rn(x, hw), y2 = __fadd_rn(y, hh);
    float cf  = (float)g_cls[idx];
    float off = __fmul_rn(cf, 7680.0f);
    float ox1 = __fadd_rn(x1, off), oy1 = __fadd_rn(y1, off);
    float ox2 = __fadd_rn(x2, off), oy2 = __fadd_rn(y2, off);
    g_box[r]  = make_float4(x1, y1, x2, y2);
    g_boff[r] = make_float4(ox1, oy1, ox2, oy2);
    g_area[r] = __fmul_rn(__fsub_rn(ox2, ox1), __fsub_rn(oy2, oy1));
    g_sc[r] = sc;
    g_cf[r] = cf;
    if (!(sc > CONF_T))
        atomicOr(&g_rem0[r >> 6], 1ULL << (r & 63));
}

// 7. suppression bitmask, triangular (only words w >= i/64 computed)
__global__ void __launch_bounds__(256) k_iou() {
    __shared__ float4 sb[KTOP];
    __shared__ float  sa[KTOP];
    for (int kx = threadIdx.x; kx < KTOP; kx += 256) {
        sb[kx] = g_boff[kx];
        sa[kx] = g_area[kx];
    }
    __syncthreads();
    int t = blockIdx.x * 256 + threadIdx.x;   // 65536 threads
    int i = t >> 5, w = t & 31;
    if (w < (i >> 6)) { g_mask[i * 32 + w] = 0ULL; return; }
    float4 a  = sb[i];
    float  fa = sa[i];
    u64 bits = 0ULL;
    int j0 = w << 6;
#pragma unroll 8
    for (int jj = 0; jj < 64; ++jj) {
        int j = j0 + jj;
        if (j <= i) continue;
        float4 b = sb[j];
        float ltx = fmaxf(a.x, b.x), lty = fmaxf(a.y, b.y);
        float rbx = fminf(a.z, b.z), rby = fminf(a.w, b.w);
        float wx = fmaxf(__fsub_rn(rbx, ltx), 0.0f);
        float wy = fmaxf(__fsub_rn(rby, lty), 0.0f);
        float inter = __fmul_rn(wx, wy);
        float den = __fadd_rn(__fsub_rn(__fadd_rn(fa, sa[j]), inter), 1e-7f);
        if (__fdiv_rn(inter, den) > IOU_T) bits |= (1ULL << jj);
    }
    g_mask[i * 32 + w] = bits;
}

// 8. greedy NMS (warp 0, pipelined + fast path) fused with final writeback
__global__ void __launch_bounds__(64) k_nms(float* __restrict__ out) {
    __shared__ u64 dmx[32];
    __shared__ u64 srem[32];
    __shared__ int swpre[32];
    int tid = threadIdx.x;

    if (tid < 32) {
        int lane = tid;
        u64 rem = g_rem0[lane];
        u64 A[32], B[32];

#define LOADCH(dst, cc) { int _base = (cc) << 5;                              \
    _Pragma("unroll") for (int b = 0; b < 32; ++b)                            \
        dst[b] = g_mask[(u32)(_base + b) * 32 + lane]; }

#define PROC(M, HALF, WD) {                                                   \
    __syncwarp();                                                             \
    if (lane == (WD)) { _Pragma("unroll")                                     \
        for (int b = 0; b < 32; ++b) dmx[b] = M[b]; }                         \
    __syncwarp();                                                             \
    u32 d32[32]; u32 orall = 0u;                                              \
    _Pragma("unroll") for (int b = 0; b < 32; ++b) {                          \
        d32[b] = (u32)(dmx[b] >> (HALF)); orall |= d32[b]; }                  \
    u32 r32 = (u32)(__shfl_sync(0xffffffffu, rem, (WD)) >> (HALF));           \
    u32 kmask;                                                                \
    if (orall == 0u) kmask = ~r32;                                            \
    else { kmask = 0u;                                                        \
        _Pragma("unroll") for (int b = 0; b < 32; ++b) {                      \
            if (!((r32 >> b) & 1u)) { kmask |= (1u << b); r32 |= d32[b]; } } }\
    u64 acc = 0ULL;                                                           \
    _Pragma("unroll") for (int b = 0; b < 32; ++b)                            \
        if (kmask & (1u << b)) acc |= M[b];                                   \
    rem |= acc; }

        LOADCH(A, 0)
        for (int c = 0; c < 64; c += 2) {
            LOADCH(B, c + 1)                 // prefetch odd chunk
            int wd = c >> 1;
            PROC(A, 0, wd)
            int c2 = (c + 2 < 64) ? c + 2 : 62;
            LOADCH(A, c2)                    // prefetch next even chunk
            PROC(B, 32, wd)
        }
#undef LOADCH
#undef PROC
        srem[lane] = rem;
        int cnt = __popcll(~rem);
        int pre = cnt;
#pragma unroll
        for (int o = 1; o < 32; o <<= 1) {
            int v = __shfl_up_sync(0xffffffffu, pre, o);
            if (lane >= o) pre += v;
        }
        swpre[lane] = pre - cnt;             // exclusive prefix of kept counts
    }
    __syncthreads();

    for (int r = tid; r < KTOP; r += 64) {
        u64 kb = ~srem[r >> 6];
        if ((kb >> (r & 63)) & 1ULL) {
            int pos = swpre[r >> 6] + __popcll(kb & ((1ULL << (r & 63)) - 1ULL));
            if (pos < MAXDET) {
                float4 b = g_box[r];
                out[pos * 6 + 0] = b.x;
                out[pos * 6 + 1] = b.y;
                out[pos * 6 + 2] = b.z;
                out[pos * 6 + 3] = b.w;
                out[pos * 6 + 4] = g_sc[r];
                out[pos * 6 + 5] = g_cf[r];
            }
        }
    }
}

// ------------------------------ launch --------------------------------------
extern "C" void kernel_launch(void* const* d_in, const int* in_sizes, int n_in,
                              void* d_out, int out_size) {
    const int*   img  = (const int*)d_in[0];
    const float* pred = (const float*)d_in[1];
    float*       out  = (float*)d_out;

    k_pre    <<< (IMG_ELEMS + 255) / 256, 256 >>> (img, out);
    k_scores <<< (NANCH + 255) / 256, 256 >>> (pred);
    k_thresh <<< 1, 1024 >>> ();
    k_compact<<< (NANCH + 255) / 256, 256 >>> ();
    k_rank   <<< dim3(CAP / 1024, CAP / 1024), 1024 >>> ();
    k_gather <<< CAP / 1024, 1024 >>> (pred);
    k_iou    <<< 256, 256 >>> ();
    k_nms    <<< 1, 64 >>> (out);
}

// round 3
// speedup vs baseline: 2.5435x; 1.3358x over previous
#include <cuda_runtime.h>
#include <cstdint>

typedef unsigned long long u64;
typedef unsigned int u32;

// ---------------------------------------------------------------------------
// GhInfer_19104014533112 : YOLO NMS post-process on GB300
// out[0:6000) det (1000x6) fp32 ; out[6000:1234800) img (1,3,640,640) fp32
// in[0] img int32 (640*640*3) ; in[1] pred fp32 (8*25200*85), batch 0 only
// ---------------------------------------------------------------------------

#define NANCH 25200
#define NCLS  80
#define KTOP  2048
#define NBINS 16384
#define CAP   8192
#define MAXDET 1000
#define CONF_T 0.4f
#define IOU_T  0.45f
#define NPIX  (640*640)
#define PREB  1600                 // NPIX / 256 pixel blocks
#define SCB   99                   // score blocks (99*8 warps*32 anchors)
#define BIN_BASE 0x2FB3            // bin of scores just above 0.4
#define BIN_NEG  0x101F            // bin of -1.0f

// ------------------------- device scratch (no allocs) ----------------------
__device__ u32    g_msc[NANCH];
__device__ int    g_cls[NANCH];
__device__ int    g_hist[NBINS];
__device__ int    g_count;
__device__ u64    g_keys[CAP];
__device__ int    g_rank[CAP];
__device__ float4 g_box[KTOP];
__device__ float4 g_boff[KTOP];
__device__ float  g_area[KTOP];
__device__ float  g_sc[KTOP];
__device__ float  g_cf[KTOP];
__device__ u64    g_mask[KTOP*32];
__device__ u32    g_nzw[KTOP];     // per-row bitmap of nonzero mask words
__device__ u64    g_rem0[32];

__device__ __forceinline__ u32 f2u(float f) {
    u32 b = __float_as_uint(f);
    return (b & 0x80000000u) ? ~b : (b | 0x80000000u);
}
__device__ __forceinline__ float u2f(u32 u) {
    u32 b = (u & 0x80000000u) ? (u ^ 0x80000000u) : ~u;
    return __uint_as_float(b);
}

// ---------------------------------------------------------------------------
// 1. fused: image preprocess + zero/init  |  warp-per-anchor scores+histogram
__global__ void __launch_bounds__(256) k_fused(const int* __restrict__ img,
                                               const float* __restrict__ pred,
                                               float* __restrict__ out) {
    int bid = blockIdx.x, tid = threadIdx.x;
    if (bid < PREB) {
        int p = bid * 256 + tid;                // pixel index
        int v0 = img[p * 3 + 0], v1 = img[p * 3 + 1], v2 = img[p * 3 + 2];
        out[6000 + 0 * NPIX + p] = (float)v2 / 255.0f;   // plane 0 = channel 2
        out[6000 + 1 * NPIX + p] = (float)v1 / 255.0f;
        out[6000 + 2 * NPIX + p] = (float)v0 / 255.0f;
        if (p < 6000)  out[p] = 0.0f;
        if (p < NBINS) g_hist[p] = 0;
        if (p < CAP) { g_keys[p] = (u64)(u32)p; g_rank[p] = 0; }
        if (p < 32)  g_rem0[p] = 0ULL;
        if (p == 0)  g_count = 0;
        return;
    }
    // ---- scores: one warp per anchor, 32 anchors per warp ----
    __shared__ int shist[47];
    int sb = bid - PREB;
    if (tid < 47) shist[tid] = 0;
    __syncthreads();
    int w = tid >> 5, lane = tid & 31;
    int wid = sb * 8 + w;
    for (int k = 0; k < 32; ++k) {
        int a = wid * 32 + k;
        if (a >= NANCH) break;
        const float* r = pred + (long long)a * 85;
        float obj = (lane == 0) ? r[4] : 0.0f;
        obj = __shfl_sync(0xffffffffu, obj, 0);
        float v0 = __fmul_rn(r[5  + lane], obj);
        float v1 = __fmul_rn(r[37 + lane], obj);
        u64 k0 = ((u64)f2u(v0) << 7) | (u32)(NCLS - 1 - lane);
        u64 k1 = ((u64)f2u(v1) << 7) | (u32)(NCLS - 1 - (lane + 32));
        u64 best = (k0 > k1) ? k0 : k1;
        if (lane < 16) {
            float v2 = __fmul_rn(r[69 + lane], obj);
            u64 k2 = ((u64)f2u(v2) << 7) | (u32)(NCLS - 1 - (lane + 64));
            if (k2 > best) best = k2;
        }
#pragma unroll
        for (int o = 16; o; o >>= 1) {
            u64 oth = __shfl_xor_sync(0xffffffffu, best, o);
            if (oth > best) best = oth;
        }
        if (lane == 0) {
            float m  = u2f((u32)(best >> 7));
            int   c  = NCLS - 1 - (int)(best & 0x7F);
            float sc = (m > CONF_T) ? m : -1.0f;
            u32 u = f2u(sc);
            g_msc[a] = u;
            g_cls[a] = c;
            if (sc > CONF_T) {
                int idx = (int)(u >> 18) - BIN_BASE;
                if (idx >= 0 && idx < 46) atomicAdd(&shist[idx], 1);
                else                      atomicAdd(&g_hist[u >> 18], 1);
            } else atomicAdd(&shist[46], 1);
        }
    }
    __syncthreads();
    if (tid < 46) { int v = shist[tid]; if (v) atomicAdd(&g_hist[BIN_BASE + tid], v); }
    if (tid == 46){ int v = shist[46];  if (v) atomicAdd(&g_hist[BIN_NEG], v); }
}

// ---------------------------------------------------------------------------
// 2. fused threshold (recomputed per block) + warp-aggregated compaction
__global__ void __launch_bounds__(256) k_tc() {
    __shared__ int part[256];
    __shared__ u32 sth;
    int tid = threadIdx.x;
    int s = 0;
#pragma unroll 8
    for (int b = 0; b < 64; ++b) s += g_hist[tid * 64 + b];
    part[tid] = s;
    __syncthreads();
    for (int off = 1; off < 256; off <<= 1) {
        int v = (tid + off < 256) ? part[tid + off] : 0;
        __syncthreads();
        part[tid] += v;
        __syncthreads();
    }
    int nxt = (tid < 255) ? part[tid + 1] : 0;
    if (part[tid] >= KTOP && nxt < KTOP) {
        int acc = nxt;
        for (int b = tid * 64 + 63; b >= tid * 64; --b) {
            acc += g_hist[b];
            if (acc >= KTOP) { sth = (u32)b; break; }
        }
    }
    __syncthreads();
    u32 th = sth;
    int i = blockIdx.x * 256 + tid;
    bool take = false; u32 u = 0;
    if (i < NANCH) { u = g_msc[i]; take = ((u >> 18) >= th); }
    u32 ball = __ballot_sync(0xffffffffu, take);
    int n = __popc(ball);
    int base = 0;
    if ((tid & 31) == 0 && n) base = atomicAdd(&g_count, n);
    base = __shfl_sync(0xffffffffu, base, 0);
    if (take) {
        int p = base + __popc(ball & ((1u << (tid & 31)) - 1u));
        if (p < CAP) g_keys[p] = ((u64)u << 32) | (u32)(~i);
    }
}

// ---------------------------------------------------------------------------
// 3. rank-sort (keys unique => exact top_k order); blocks beyond count exit
__global__ void __launch_bounds__(1024) k_rank() {
    int cnt = g_count; if (cnt > CAP) cnt = CAP;
    if ((int)(blockIdx.x * 1024) >= cnt) return;
    if ((int)(blockIdx.y * 1024) >= cnt) return;
    __shared__ u64 sk[1024];
    int tid = threadIdx.x;
    sk[tid] = g_keys[blockIdx.y * 1024 + tid];
    __syncthreads();
    int i = blockIdx.x * 1024 + tid;
    u64 my = g_keys[i];
    int c = 0;
#pragma unroll 16
    for (int j = 0; j < 1024; ++j)        // uniform j => smem broadcast
        c += (sk[j] > my) ? 1 : 0;
    if (c) atomicAdd(&g_rank[i], c);
}

// ---------------------------------------------------------------------------
// 4. scatter by rank + box decode
__global__ void __launch_bounds__(1024) k_gather(const float* __restrict__ pred) {
    int cnt = g_count; if (cnt > CAP) cnt = CAP;
    int i = blockIdx.x * 1024 + threadIdx.x;
    if (i >= cnt) return;
    int r = g_rank[i];
    if (r >= KTOP) return;
    u64 key = g_keys[i];
    float sc = u2f((u32)(key >> 32));
    int  idx = (int)(~(u32)key);
    const float* p = pred + (long long)idx * 85;
    float x = p[0], y = p[1], w = p[2], h = p[3];
    float hw = __fmul_rn(w, 0.5f), hh = __fmul_rn(h, 0.5f);
    float x1 = __fsub_rn(x, hw), y1 = __fsub_rn(y, hh);
    float x2 = __fadd_rn(x, hw), y2 = __fadd_rn(y, hh);
    float cf  = (float)g_cls[idx];
    float off = __fmul_rn(cf, 7680.0f);
    float ox1 = __fadd_rn(x1, off), oy1 = __fadd_rn(y1, off);
    float ox2 = __fadd_rn(x2, off), oy2 = __fadd_rn(y2, off);
    g_box[r]  = make_float4(x1, y1, x2, y2);
    g_boff[r] = make_float4(ox1, oy1, ox2, oy2);
    g_area[r] = __fmul_rn(__fsub_rn(ox2, ox1), __fsub_rn(oy2, oy1));
    g_sc[r] = sc;
    g_cf[r] = cf;
    if (!(sc > CONF_T))
        atomicOr(&g_rem0[r >> 6], 1ULL << (r & 63));
}

// ---------------------------------------------------------------------------
// 5. suppression bitmask + per-row nonzero-word bitmap
__global__ void __launch_bounds__(256) k_iou() {
    __shared__ float4 sb[KTOP];
    __shared__ float  sa[KTOP];
    for (int kx = threadIdx.x; kx < KTOP; kx += 256) {
        sb[kx] = g_boff[kx];
        sa[kx] = g_area[kx];
    }
    __syncthreads();
    int t = blockIdx.x * 256 + threadIdx.x;
    int i = t >> 5, w = t & 31;
    u64 bits = 0ULL;
    if (w >= (i >> 6)) {
        float4 a  = sb[i];
        float  fa = sa[i];
        int j0 = w << 6;
#pragma unroll 8
        for (int jj = 0; jj < 64; ++jj) {
            int j = j0 + jj;
            if (j <= i) continue;
            float4 b = sb[j];
            float ltx = fmaxf(a.x, b.x), lty = fmaxf(a.y, b.y);
            float rbx = fminf(a.z, b.z), rby = fminf(a.w, b.w);
            float wx = fmaxf(__fsub_rn(rbx, ltx), 0.0f);
            float wy = fmaxf(__fsub_rn(rby, lty), 0.0f);
            float inter = __fmul_rn(wx, wy);
            float den = __fadd_rn(__fsub_rn(__fadd_rn(fa, sa[j]), inter), 1e-7f);
            if (__fdiv_rn(inter, den) > IOU_T) bits |= (1ULL << jj);
        }
    }
    u32 ball = __ballot_sync(0xffffffffu, bits != 0ULL);
    if (bits) g_mask[i * 32 + w] = bits;     // only nonzero words ever read
    if (w == 0) g_nzw[i] = ball;
}

// ---------------------------------------------------------------------------
// 6. sparse greedy NMS + final writeback
__global__ void __launch_bounds__(256) k_nms(float* __restrict__ out) {
    __shared__ int  slist[KTOP];
    __shared__ u32  slnz[KTOP];
    __shared__ int  wcnt[8];
    __shared__ int  scnt;
    __shared__ u64  srem[32];
    __shared__ int  swpre[32];
    int tid = threadIdx.x;
    int w = tid >> 5, lane = tid & 31;

    // ---- enumerate rows with nonzero masks, in ascending order ----
    u32 nzreg[8]; u32 balls[8];
#pragma unroll
    for (int k = 0; k < 8; ++k)
        nzreg[k] = g_nzw[(w * 8 + k) * 32 + lane];
    int tot = 0;
#pragma unroll
    for (int k = 0; k < 8; ++k) {
        balls[k] = __ballot_sync(0xffffffffu, nzreg[k] != 0u);
        tot += __popc(balls[k]);
    }
    if (lane == 0) wcnt[w] = tot;
    __syncthreads();
    int off = 0;
    for (int q = 0; q < w; ++q) off += wcnt[q];
#pragma unroll
    for (int k = 0; k < 8; ++k) {
        if (nzreg[k]) {
            int pos = off + __popc(balls[k] & ((1u << lane) - 1u));
            slist[pos] = (w * 8 + k) * 32 + lane;
            slnz[pos]  = nzreg[k];
        }
        off += __popc(balls[k]);
    }
    if (tid == 0) { int s = 0; for (int q = 0; q < 8; ++q) s += wcnt[q]; scnt = s; }
    __syncthreads();

    // ---- serial greedy chain over the sparse list (warp 0) ----
    if (tid < 32) {
        int cnt = scnt;
        u64 rem = g_rem0[lane];
        u64 mA[8], mB[8];

#define LOADG(M, G0) {                                                        \
    _Pragma("unroll") for (int k = 0; k < 8; ++k) {                           \
        int e = (G0) + k; u64 v = 0ULL;                                       \
        if (e < cnt && ((slnz[e] >> lane) & 1u))                              \
            v = g_mask[(u32)slist[e] * 32 + lane];                            \
        M[k] = v; } }

#define APPLY(M, G0) {                                                        \
    _Pragma("unroll") for (int k = 0; k < 8; ++k) {                           \
        int e = (G0) + k;                                                     \
        if (e < cnt) {                                                        \
            int rr = slist[e];                                                \
            u64 remw = __shfl_sync(0xffffffffu, rem, rr >> 6);                \
            if (!((remw >> (rr & 63)) & 1ULL)) rem |= M[k];                   \
        } } }

        LOADG(mA, 0)
        for (int g = 0; g < cnt; g += 16) {
            LOADG(mB, g + 8)
            APPLY(mA, g)
            LOADG(mA, g + 16)
            APPLY(mB, g + 8)
        }
#undef LOADG
#undef APPLY
        srem[lane] = rem;
        int c = __popcll(~rem);
        int pre = c;
#pragma unroll
        for (int o = 1; o < 32; o <<= 1) {
            int v = __shfl_up_sync(0xffffffffu, pre, o);
            if (lane >= o) pre += v;
        }
        swpre[lane] = pre - c;
    }
    __syncthreads();

    // ---- compact kept rows into det output ----
    for (int r = tid; r < KTOP; r += 256) {
        u64 kb = ~srem[r >> 6];
        if ((kb >> (r & 63)) & 1ULL) {
            int pos = swpre[r >> 6] + __popcll(kb & ((1ULL << (r & 63)) - 1ULL));
            if (pos < MAXDET) {
                float4 b = g_box[r];
                out[pos * 6 + 0] = b.x;
                out[pos * 6 + 1] = b.y;
                out[pos * 6 + 2] = b.z;
                out[pos * 6 + 3] = b.w;
                out[pos * 6 + 4] = g_sc[r];
                out[pos * 6 + 5] = g_cf[r];
            }
        }
    }
}

// ------------------------------ launch --------------------------------------
extern "C" void kernel_launch(void* const* d_in, const int* in_sizes, int n_in,
                              void* d_out, int out_size) {
    const int*   img  = (const int*)d_in[0];
    const float* pred = (const float*)d_in[1];
    float*       out  = (float*)d_out;

    k_fused  <<< PREB + SCB, 256 >>> (img, pred, out);
    k_tc     <<< (NANCH + 255) / 256, 256 >>> ();
    k_rank   <<< dim3(CAP / 1024, CAP / 1024), 1024 >>> ();
    k_gather <<< CAP / 1024, 1024 >>> (pred);
    k_iou    <<< 256, 256 >>> ();
    k_nms    <<< 1, 256 >>> (out);
}

// round 5
// speedup vs baseline: 5.4816x; 2.1552x over previous
#include <cuda_runtime.h>
#include <cstdint>

typedef unsigned long long u64;
typedef unsigned int u32;

// ---------------------------------------------------------------------------
// GhInfer_19104014533112 : YOLO NMS post-process on GB300
// out[0:6000) det (1000x6) fp32 ; out[6000:1234800) img (1,3,640,640) fp32
// in[0] img int32 (640*640*3) ; in[1] pred fp32 (8*25200*85), batch 0 only
// ---------------------------------------------------------------------------

#define NANCH 25200
#define NCLS  80
#define KTOP  2048
#define NBINS 16384
#define CAP   8192
#define PCAP  4096
#define MAXDET 1000
#define CONF_T 0.4f
#define IOU_T  0.45f
#define NPIX  (640*640)
#define PREB  1600                 // NPIX/256 pixel blocks
#define SCB   788                  // score blocks: 8 warps x 4 anchors = 32/blk
#define BIN_BASE 0x2FB3            // bin of scores just above 0.4
#define BIN_NEG  0x101F            // bin of -1.0f

// ------------------------- device scratch (no allocs) ----------------------
__device__ u32    g_msc[NANCH];
__device__ int    g_cls[NANCH];
__device__ int    g_hist[NBINS];
__device__ int    g_count;
__device__ u64    g_keys[CAP];
__device__ float4 g_box[KTOP];
__device__ float4 g_boff[KTOP];
__device__ float  g_area[KTOP];
__device__ float  g_sc[KTOP];
__device__ float  g_cf[KTOP];
__device__ u32    g_keep[64];      // keep bit per rank (2048 bits)
__device__ u32    g_pairs[PCAP];   // suppression pairs (i<<11)|j, i<j
__device__ int    g_np;

__device__ __forceinline__ u32 f2u(float f) {
    u32 b = __float_as_uint(f);
    return (b & 0x80000000u) ? ~b : (b | 0x80000000u);
}
__device__ __forceinline__ float u2f(u32 u) {
    u32 b = (u & 0x80000000u) ? (u ^ 0x80000000u) : ~u;
    return __uint_as_float(b);
}

// ---------------------------------------------------------------------------
// 1. fused: image preprocess + zero/init  |  warp-per-4-anchors scores+hist
__global__ void __launch_bounds__(256) k_fused(const int* __restrict__ img,
                                               const float* __restrict__ pred,
                                               float* __restrict__ out) {
    int bid = blockIdx.x, tid = threadIdx.x;
    if (bid < PREB) {
        int p = bid * 256 + tid;                // pixel index
        int v0 = img[p * 3 + 0], v1 = img[p * 3 + 1], v2 = img[p * 3 + 2];
        out[6000 + 0 * NPIX + p] = (float)v2 / 255.0f;   // plane 0 = channel 2
        out[6000 + 1 * NPIX + p] = (float)v1 / 255.0f;
        out[6000 + 2 * NPIX + p] = (float)v0 / 255.0f;
        if (p < 6000)  out[p] = 0.0f;
        if (p < NBINS) g_hist[p] = 0;
        if (p < 64)    g_keep[p] = 0u;
        if (p == 0)  { g_count = 0; g_np = 0; }
        return;
    }
    // ---- scores: one warp per 4 anchors ----
    __shared__ int shist[47];
    int sb = bid - PREB;
    if (tid < 47) shist[tid] = 0;
    __syncthreads();
    int w = tid >> 5, lane = tid & 31;
    int wid = sb * 8 + w;
#pragma unroll
    for (int k = 0; k < 4; ++k) {
        int a = wid * 4 + k;
        if (a >= NANCH) break;
        const float* r = pred + (long long)a * 85;
        float obj = __shfl_sync(0xffffffffu, (lane == 0) ? r[4] : 0.0f, 0);
        float v0 = __fmul_rn(r[5  + lane], obj);
        float v1 = __fmul_rn(r[37 + lane], obj);
        u64 k0 = ((u64)f2u(v0) << 7) | (u32)(NCLS - 1 - lane);
        u64 k1 = ((u64)f2u(v1) << 7) | (u32)(NCLS - 1 - (lane + 32));
        u64 best = (k0 > k1) ? k0 : k1;
        if (lane < 16) {
            float v2 = __fmul_rn(r[69 + lane], obj);
            u64 k2 = ((u64)f2u(v2) << 7) | (u32)(NCLS - 1 - (lane + 64));
            if (k2 > best) best = k2;
        }
#pragma unroll
        for (int o = 16; o; o >>= 1) {
            u64 oth = __shfl_xor_sync(0xffffffffu, best, o);
            if (oth > best) best = oth;
        }
        if (lane == 0) {
            float m  = u2f((u32)(best >> 7));
            int   c  = NCLS - 1 - (int)(best & 0x7F);
            float sc = (m > CONF_T) ? m : -1.0f;
            u32 u = f2u(sc);
            g_msc[a] = u;
            g_cls[a] = c;
            if (sc > CONF_T) {
                int idx = (int)(u >> 18) - BIN_BASE;
                if (idx >= 0 && idx < 46) atomicAdd(&shist[idx], 1);
                else                      atomicAdd(&g_hist[u >> 18], 1);
            } else atomicAdd(&shist[46], 1);
        }
    }
    __syncthreads();
    if (tid < 46) { int v = shist[tid]; if (v) atomicAdd(&g_hist[BIN_BASE + tid], v); }
    if (tid == 46){ int v = shist[46];  if (v) atomicAdd(&g_hist[BIN_NEG], v); }
}

// ---------------------------------------------------------------------------
// 2. fused threshold (recomputed per block) + warp-aggregated compaction
__global__ void __launch_bounds__(256) k_tc() {
    __shared__ int part[256];
    __shared__ u32 sth;
    int tid = threadIdx.x;
    int s = 0;
#pragma unroll 8
    for (int b = 0; b < 64; ++b) s += g_hist[tid * 64 + b];
    part[tid] = s;
    __syncthreads();
    for (int off = 1; off < 256; off <<= 1) {
        int v = (tid + off < 256) ? part[tid + off] : 0;
        __syncthreads();
        part[tid] += v;
        __syncthreads();
    }
    int nxt = (tid < 255) ? part[tid + 1] : 0;
    if (part[tid] >= KTOP && nxt < KTOP) {
        int acc = nxt;
        for (int b = tid * 64 + 63; b >= tid * 64; --b) {
            acc += g_hist[b];
            if (acc >= KTOP) { sth = (u32)b; break; }
        }
    }
    __syncthreads();
    u32 th = sth;
    int i = blockIdx.x * 256 + tid;
    bool take = false; u32 u = 0;
    if (i < NANCH) { u = g_msc[i]; take = ((u >> 18) >= th); }
    u32 ball = __ballot_sync(0xffffffffu, take);
    int n = __popc(ball);
    int base = 0;
    if ((tid & 31) == 0 && n) base = atomicAdd(&g_count, n);
    base = __shfl_sync(0xffffffffu, base, 0);
    if (take) {
        int p = base + __popc(ball & ((1u << (tid & 31)) - 1u));
        if (p < CAP) g_keys[p] = ((u64)u << 32) | (u32)(~i);
    }
}

// ---------------------------------------------------------------------------
// 3. lane-parallel rank + fused gather/decode (one warp per candidate)
__global__ void __launch_bounds__(256) k_rg(const float* __restrict__ pred) {
    int cnt = g_count; if (cnt > CAP) cnt = CAP;
    int gw = blockIdx.x * 8 + (threadIdx.x >> 5);    // global warp = candidate
    int lane = threadIdx.x & 31;
    if (gw >= cnt) return;
    u64 my = g_keys[gw];
    int c = 0;
    for (int j = lane; j < cnt; j += 32)
        c += (__ldg(&g_keys[j]) > my) ? 1 : 0;
#pragma unroll
    for (int o = 16; o; o >>= 1)
        c += __shfl_xor_sync(0xffffffffu, c, o);
    int r = c;                                  // exact unique rank
    if (r >= KTOP || lane != 0) return;
    float sc = u2f((u32)(my >> 32));
    int  idx = (int)(~(u32)my);
    const float* p = pred + (long long)idx * 85;
    float x = p[0], y = p[1], w = p[2], h = p[3];
    float hw = __fmul_rn(w, 0.5f), hh = __fmul_rn(h, 0.5f);
    float x1 = __fsub_rn(x, hw), y1 = __fsub_rn(y, hh);
    float x2 = __fadd_rn(x, hw), y2 = __fadd_rn(y, hh);
    float cf  = (float)g_cls[idx];
    float off = __fmul_rn(cf, 7680.0f);
    float ox1 = __fadd_rn(x1, off), oy1 = __fadd_rn(y1, off);
    float ox2 = __fadd_rn(x2, off), oy2 = __fadd_rn(y2, off);
    g_box[r]  = make_float4(x1, y1, x2, y2);
    g_boff[r] = make_float4(ox1, oy1, ox2, oy2);
    g_area[r] = __fmul_rn(__fsub_rn(ox2, ox1), __fsub_rn(oy2, oy1));
    g_sc[r] = sc;
    g_cf[r] = cf;
    if (sc > CONF_T)
        atomicOr(&g_keep[r >> 5], 1u << (r & 31));
}

// ---------------------------------------------------------------------------
// 4. suppression pairs, same-class only (cross-class IoU provably == 0:
//    class offset 7680 > max box extent, so inter == 0 -> 0/den <= 0.45)
__global__ void __launch_bounds__(256) k_pairs() {
    __shared__ int    scnt;
    __shared__ short  rows[256];
    __shared__ float4 bx[256];
    __shared__ float  ar[256];
    int c = blockIdx.x, tid = threadIdx.x;
    if (tid == 0) scnt = 0;
    __syncthreads();
    for (int r = tid; r < KTOP; r += 256) {
        if (g_sc[r] > CONF_T && (int)g_cf[r] == c) {
            int p = atomicAdd(&scnt, 1);
            if (p < 256) {
                rows[p] = (short)r;
                bx[p]   = g_boff[r];
                ar[p]   = g_area[r];
            }
        }
    }
    __syncthreads();
    int m = scnt; if (m > 256) m = 256;
    for (int t = tid; t < m * m; t += 256) {
        int a = t / m, b = t - a * m;
        if (a >= b) continue;
        float4 A = bx[a], B = bx[b];
        float ltx = fmaxf(A.x, B.x), lty = fmaxf(A.y, B.y);
        float rbx = fminf(A.z, B.z), rby = fminf(A.w, B.w);
        float wx = fmaxf(__fsub_rn(rbx, ltx), 0.0f);
        float wy = fmaxf(__fsub_rn(rby, lty), 0.0f);
        float inter = __fmul_rn(wx, wy);
        if (inter <= 0.0f) continue;            // iou = 0 exactly
        float den = __fadd_rn(__fsub_rn(__fadd_rn(ar[a], ar[b]), inter), 1e-7f);
        if (__fdiv_rn(inter, den) > IOU_T) {
            int i = rows[a], j = rows[b];
            if (i > j) { int s = i; i = j; j = s; }
            int p = atomicAdd(&g_np, 1);
            if (p < PCAP) g_pairs[p] = ((u32)i << 11) | (u32)j;
        }
    }
}

// ---------------------------------------------------------------------------
// 5. sort pairs + greedy sequential suppression + compacted writeback
__global__ void __launch_bounds__(1024) k_nms(float* __restrict__ out) {
    __shared__ u32 sp[PCAP];
    __shared__ u32 keep[64];
    __shared__ int wpre[64];
    int tid = threadIdx.x;
    int np = g_np; if (np > PCAP) np = PCAP;
    if (tid < 64) keep[tid] = g_keep[tid];
    int npad = 1; while (npad < np) npad <<= 1;
    for (int i = tid; i < npad; i += 1024)
        sp[i] = (i < np) ? g_pairs[i] : 0xFFFFFFFFu;
    __syncthreads();
    for (int k = 2; k <= npad; k <<= 1) {
        for (int j = k >> 1; j; j >>= 1) {
            for (int i = tid; i < npad; i += 1024) {
                int x = i ^ j;
                if (x > i) {
                    u32 a = sp[i], b = sp[x];
                    bool up = ((i & k) == 0);
                    if (up ? (a > b) : (a < b)) { sp[i] = b; sp[x] = a; }
                }
            }
            __syncthreads();
        }
    }
    if (tid == 0) {   // greedy chain: ascending suppressor rank == reference
        for (int p = 0; p < np; ++p) {
            u32 v = sp[p];
            int i = (int)(v >> 11), j = (int)(v & 2047u);
            if ((keep[i >> 5] >> (i & 31)) & 1u)
                keep[j >> 5] &= ~(1u << (j & 31));
        }
    }
    __syncthreads();
    if (tid == 0) {
        int s = 0;
        for (int w = 0; w < 64; ++w) { wpre[w] = s; s += __popc(keep[w]); }
    }
    __syncthreads();
    for (int r = tid; r < KTOP; r += 1024) {
        u32 kw = keep[r >> 5];
        if ((kw >> (r & 31)) & 1u) {
            int pos = wpre[r >> 5] + __popc(kw & ((1u << (r & 31)) - 1u));
            if (pos < MAXDET) {
                float4 b = g_box[r];
                out[pos * 6 + 0] = b.x;
                out[pos * 6 + 1] = b.y;
                out[pos * 6 + 2] = b.z;
                out[pos * 6 + 3] = b.w;
                out[pos * 6 + 4] = g_sc[r];
                out[pos * 6 + 5] = g_cf[r];
            }
        }
    }
}

// ------------------------------ launch --------------------------------------
extern "C" void kernel_launch(void* const* d_in, const int* in_sizes, int n_in,
                              void* d_out, int out_size) {
    const int*   img  = (const int*)d_in[0];
    const float* pred = (const float*)d_in[1];
    float*       out  = (float*)d_out;

    k_fused  <<< PREB + SCB, 256 >>> (img, pred, out);
    k_tc     <<< (NANCH + 255) / 256, 256 >>> ();
    k_rg     <<< CAP / 8, 256 >>> (pred);        // 1024 blocks x 8 warps: warp/cand
    k_pairs  <<< NCLS, 256 >>> ();
    k_nms    <<< 1, 1024 >>> (out);
}